// round 5
// baseline (speedup 1.0000x reference)
#include <cuda_runtime.h>

// Segmented mean-pool: out[b, :] = mean over rows of `samples` owned by bag b.
// samples: [T, 512] fp32 (256 MB)  -> streaming HBM-bound.
// counts:  [B] int64 (or int32 - auto-detected).
// out:     [B, 512] fp32.

#define D_DIM 512
#define COLS4 (D_DIM / 4)          // 128 float4 columns
#define THREADS 128                // one float4 column per thread
#define ROWS_PER_BLOCK 16          // small chunks -> multi-wave, smooth tail
#define MAX_BAGS 128

__device__ int   g_prefix[MAX_BAGS + 1];
__device__ float g_inv[MAX_BAGS];

// ---------------------------------------------------------------------------
// init: zero the output (all blocks); block 0 warp 0 detects counts dtype and
// builds the prefix scan + 1/count via warp shfl.
// ---------------------------------------------------------------------------
__global__ void init_kernel(const void* __restrict__ counts_raw,
                            float* __restrict__ out,
                            int n_bags, int out_n, int total_rows) {
    for (int gid = blockIdx.x * blockDim.x + threadIdx.x; gid < out_n;
         gid += gridDim.x * blockDim.x)
        out[gid] = 0.0f;

    if (blockIdx.x != 0 || threadIdx.x >= 32) return;
    int t = threadIdx.x;

    // dtype detect: does the int64 interpretation sum to total_rows?
    long long sum64 = 0;
    for (int i = t; i < n_bags; i += 32)
        sum64 += ((const long long*)counts_raw)[i];
    #pragma unroll
    for (int off = 16; off; off >>= 1)
        sum64 += __shfl_xor_sync(0xffffffffu, sum64, off);
    bool use32 = (sum64 != (long long)total_rows);

    // inclusive warp scan in chunks of 32 with carry
    long long carry = 0;
    for (int base = 0; base < n_bags; base += 32) {
        int idx = base + t;
        long long c = 0;
        if (idx < n_bags)
            c = use32 ? (long long)((const int*)counts_raw)[idx]
                      : ((const long long*)counts_raw)[idx];
        long long v = c;
        #pragma unroll
        for (int off = 1; off < 32; off <<= 1) {
            long long u = __shfl_up_sync(0xffffffffu, v, off);
            if (t >= off) v += u;
        }
        v += carry;
        if (idx < n_bags) {
            g_prefix[idx + 1] = (int)v;
            g_inv[idx] = (c > 0) ? (float)(1.0 / (double)c) : 0.0f;
        }
        carry = __shfl_sync(0xffffffffu, v, 31);
    }
    if (t == 0) g_prefix[0] = 0;
}

// ---------------------------------------------------------------------------
// main pool: each CTA streams ROWS_PER_BLOCK contiguous rows; thread t owns
// float4 column t (coalesced 2048B/row/CTA). Segment-wise inner loop with two
// independent accumulator chains; partial sums pre-scaled by 1/count and
// flushed via atomicAdd.
// ---------------------------------------------------------------------------
__global__ void __launch_bounds__(THREADS)
pool_kernel(const float4* __restrict__ samples, float* __restrict__ out,
            int n_bags, int total_rows) {
    __shared__ int s_pref[MAX_BAGS + 1];
    int t = threadIdx.x;
    if (t <= n_bags) s_pref[t] = g_prefix[t];
    __syncthreads();

    int row0 = blockIdx.x * ROWS_PER_BLOCK;
    int row1 = row0 + ROWS_PER_BLOCK;
    if (row1 > total_rows) row1 = total_rows;
    if (row0 >= row1) return;

    // binary search: largest bag with s_pref[bag] <= row0
    int lo = 0, hi = n_bags;
    while (hi - lo > 1) {
        int mid = (lo + hi) >> 1;
        if (s_pref[mid] <= row0) lo = mid; else hi = mid;
    }
    int bag = lo;

    const int col = t;  // float4 column index
    int r = row0;
    while (r < row1) {
        int bag_end = s_pref[bag + 1];
        int seg_end = (bag_end < row1) ? bag_end : row1;
        float inv = g_inv[bag];

        float4 acc0 = make_float4(0.f, 0.f, 0.f, 0.f);
        float4 acc1 = make_float4(0.f, 0.f, 0.f, 0.f);
        const float4* p = samples + (size_t)r * COLS4 + col;
        int n = seg_end - r;
        int i = 0;
        for (; i + 1 < n; i += 2) {
            float4 a = __ldcs(p);
            float4 b = __ldcs(p + COLS4);
            p += 2 * COLS4;
            acc0.x += a.x; acc0.y += a.y; acc0.z += a.z; acc0.w += a.w;
            acc1.x += b.x; acc1.y += b.y; acc1.z += b.z; acc1.w += b.w;
        }
        if (i < n) {
            float4 a = __ldcs(p);
            acc0.x += a.x; acc0.y += a.y; acc0.z += a.z; acc0.w += a.w;
        }
        r = seg_end;

        float* o = out + (size_t)bag * D_DIM + col * 4;
        atomicAdd(o + 0, (acc0.x + acc1.x) * inv);
        atomicAdd(o + 1, (acc0.y + acc1.y) * inv);
        atomicAdd(o + 2, (acc0.z + acc1.z) * inv);
        atomicAdd(o + 3, (acc0.w + acc1.w) * inv);

        // advance to the bag containing row r (skip any zero-size bags)
        if (r < row1) {
            ++bag;
            while (s_pref[bag + 1] <= r) ++bag;
        }
    }
}

extern "C" void kernel_launch(void* const* d_in, const int* in_sizes, int n_in,
                              void* d_out, int out_size) {
    const float* samples = (const float*)d_in[0];
    const void*  counts  = d_in[1];
    float*       out     = (float*)d_out;

    int n_bags = in_sizes[1];
    if (n_bags > MAX_BAGS) n_bags = MAX_BAGS;
    int total_rows = in_sizes[0] / D_DIM;

    init_kernel<<<64, 512>>>(counts, out, n_bags, out_size, total_rows);

    int nblocks = (total_rows + ROWS_PER_BLOCK - 1) / ROWS_PER_BLOCK;
    pool_kernel<<<nblocks, THREADS>>>((const float4*)samples, out,
                                      n_bags, total_rows);
}

// round 8
// speedup vs baseline: 1.0057x; 1.0057x over previous
#include <cuda_runtime.h>

// Segmented mean-pool: out[b, :] = mean over rows of `samples` owned by bag b.
// samples: [T, 512] fp32 (256 MB)  -> streaming HBM-bound.
// counts:  [B] int64 (or int32 - auto-detected).
// out:     [B, 512] fp32.
//
// Persistent-CTA design: 2048 resident CTAs; work-stealing via a global
// atomic counter over 16-row chunks. Per-CTA setup (prefix smem fill) is paid
// once; tail idle is bounded by one chunk instead of spread x full stream.

#define D_DIM 512
#define COLS4 (D_DIM / 4)          // 128 float4 columns
#define THREADS 128                // one float4 column per thread
#define CHUNK_ROWS 16              // work-stealing granule (32 KB)
#define GRID_CTAS 2048             // single resident wave (<= 148*16)
#define MAX_BAGS 128

__device__ int          g_prefix[MAX_BAGS + 1];
__device__ float        g_inv[MAX_BAGS];
__device__ unsigned int g_counter;

// ---------------------------------------------------------------------------
// init: zero output + work counter; block 0 warp 0 detects counts dtype and
// builds the prefix scan + 1/count via warp shfl.
// ---------------------------------------------------------------------------
__global__ void init_kernel(const void* __restrict__ counts_raw,
                            float* __restrict__ out,
                            int n_bags, int out_n, int total_rows) {
    for (int gid = blockIdx.x * blockDim.x + threadIdx.x; gid < out_n;
         gid += gridDim.x * blockDim.x)
        out[gid] = 0.0f;

    if (blockIdx.x != 0 || threadIdx.x >= 32) return;
    int t = threadIdx.x;
    if (t == 0) g_counter = 0u;

    // dtype detect: does the int64 interpretation sum to total_rows?
    long long sum64 = 0;
    for (int i = t; i < n_bags; i += 32)
        sum64 += ((const long long*)counts_raw)[i];
    #pragma unroll
    for (int off = 16; off; off >>= 1)
        sum64 += __shfl_xor_sync(0xffffffffu, sum64, off);
    bool use32 = (sum64 != (long long)total_rows);

    // inclusive warp scan in chunks of 32 with carry
    long long carry = 0;
    for (int base = 0; base < n_bags; base += 32) {
        int idx = base + t;
        long long c = 0;
        if (idx < n_bags)
            c = use32 ? (long long)((const int*)counts_raw)[idx]
                      : ((const long long*)counts_raw)[idx];
        long long v = c;
        #pragma unroll
        for (int off = 1; off < 32; off <<= 1) {
            long long u = __shfl_up_sync(0xffffffffu, v, off);
            if (t >= off) v += u;
        }
        v += carry;
        if (idx < n_bags) {
            g_prefix[idx + 1] = (int)v;
            g_inv[idx] = (c > 0) ? (float)(1.0 / (double)c) : 0.0f;
        }
        carry = __shfl_sync(0xffffffffu, v, 31);
    }
    if (t == 0) g_prefix[0] = 0;
}

// ---------------------------------------------------------------------------
// persistent pool: CTA grabs 16-row chunks from the global counter. Thread t
// owns float4 column t (coalesced 2048B/row/CTA). Segment-wise inner loop,
// two independent accumulator chains; partials pre-scaled by 1/count and
// flushed via atomicAdd.
// ---------------------------------------------------------------------------
__global__ void __launch_bounds__(THREADS)
pool_kernel(const float4* __restrict__ samples, float* __restrict__ out,
            int n_bags, int total_rows, int n_chunks) {
    __shared__ int s_pref[MAX_BAGS + 1];
    __shared__ unsigned int s_chunk;
    const int t = threadIdx.x;
    if (t <= n_bags) s_pref[t] = g_prefix[t];
    // first use of s_pref is after the __syncthreads below

    for (;;) {
        if (t == 0) s_chunk = atomicAdd(&g_counter, 1u);
        __syncthreads();
        unsigned int chunk = s_chunk;
        __syncthreads();
        if (chunk >= (unsigned)n_chunks) return;

        int row0 = (int)chunk * CHUNK_ROWS;
        int row1 = row0 + CHUNK_ROWS;
        if (row1 > total_rows) row1 = total_rows;

        // binary search: largest bag with s_pref[bag] <= row0
        int lo = 0, hi = n_bags;
        while (hi - lo > 1) {
            int mid = (lo + hi) >> 1;
            if (s_pref[mid] <= row0) lo = mid; else hi = mid;
        }
        int bag = lo;

        int r = row0;
        while (r < row1) {
            int bag_end = s_pref[bag + 1];
            int seg_end = (bag_end < row1) ? bag_end : row1;
            float inv = g_inv[bag];

            float4 acc0 = make_float4(0.f, 0.f, 0.f, 0.f);
            float4 acc1 = make_float4(0.f, 0.f, 0.f, 0.f);
            const float4* p = samples + (size_t)r * COLS4 + t;
            int n = seg_end - r;
            int i = 0;
            for (; i + 1 < n; i += 2) {
                float4 a = __ldcs(p);
                float4 b = __ldcs(p + COLS4);
                p += 2 * COLS4;
                acc0.x += a.x; acc0.y += a.y; acc0.z += a.z; acc0.w += a.w;
                acc1.x += b.x; acc1.y += b.y; acc1.z += b.z; acc1.w += b.w;
            }
            if (i < n) {
                float4 a = __ldcs(p);
                acc0.x += a.x; acc0.y += a.y; acc0.z += a.z; acc0.w += a.w;
            }
            r = seg_end;

            float* o = out + (size_t)bag * D_DIM + t * 4;
            atomicAdd(o + 0, (acc0.x + acc1.x) * inv);
            atomicAdd(o + 1, (acc0.y + acc1.y) * inv);
            atomicAdd(o + 2, (acc0.z + acc1.z) * inv);
            atomicAdd(o + 3, (acc0.w + acc1.w) * inv);

            if (r < row1) {
                ++bag;
                while (s_pref[bag + 1] <= r) ++bag;
            }
        }
    }
}

extern "C" void kernel_launch(void* const* d_in, const int* in_sizes, int n_in,
                              void* d_out, int out_size) {
    const float* samples = (const float*)d_in[0];
    const void*  counts  = d_in[1];
    float*       out     = (float*)d_out;

    int n_bags = in_sizes[1];
    if (n_bags > MAX_BAGS) n_bags = MAX_BAGS;
    int total_rows = in_sizes[0] / D_DIM;
    int n_chunks = (total_rows + CHUNK_ROWS - 1) / CHUNK_ROWS;

    init_kernel<<<64, 512>>>(counts, out, n_bags, out_size, total_rows);

    int nblocks = GRID_CTAS;
    if (nblocks > n_chunks) nblocks = n_chunks;
    pool_kernel<<<nblocks, THREADS>>>((const float4*)samples, out,
                                      n_bags, total_rows, n_chunks);
}